// round 7
// baseline (speedup 1.0000x reference)
#include <cuda_runtime.h>
#include <math.h>

#define HWPX 16384      // 128*128
#define NIMG 2048       // 128 bg * 16 c
#define NBG  128
#define EPSF 1e-5f

// ---------------- scratch (static __device__, no allocations) ----------------
__device__ float  d_hw[NIMG * 256];    // [img][l]: l<128 row means, l>=128 col means
__device__ float  d_s1[NIMG * 256];    // silu(hw1): [img][l]
__device__ float  d_s2[NIMG * 256];    // silu(hw2)
__device__ float4 d_stats[NIMG];       // (S1, Q1, S2, Q2)
__device__ float  d_k1[NIMG];
__device__ float  d_k2[NIMG];
__device__ float  d_Cc[NBG];

__device__ __forceinline__ float siluf(float v) { return v / (1.0f + __expf(-v)); }

// ================= K1: per-image row means + col means =================
// grid 2048 x 256. Reverse img order so K1's last-read images are K3's first.
__global__ __launch_bounds__(256) void k1_means(const float* __restrict__ x) {
    const int img = 2047 - blockIdx.x;
    const float* g = x + (size_t)img * HWPX;
    const int lane = threadIdx.x & 31, w = threadIdx.x >> 5;   // 8 warps
    __shared__ float colp[8][128];

    float4 cs = make_float4(0.f, 0.f, 0.f, 0.f);
    #pragma unroll
    for (int k = 0; k < 16; k += 4) {
        float4 v[4]; float r[4];
        #pragma unroll
        for (int t = 0; t < 4; t++)
            v[t] = __ldg((const float4*)(g + (w + 8 * (k + t)) * 128) + lane);
        #pragma unroll
        for (int t = 0; t < 4; t++) {
            cs.x += v[t].x; cs.y += v[t].y; cs.z += v[t].z; cs.w += v[t].w;
            r[t] = (v[t].x + v[t].y) + (v[t].z + v[t].w);
        }
        #pragma unroll
        for (int off = 16; off; off >>= 1) {
            #pragma unroll
            for (int t = 0; t < 4; t++) r[t] += __shfl_down_sync(0xffffffffu, r[t], off);
        }
        if (lane == 0) {
            #pragma unroll
            for (int t = 0; t < 4; t++)
                d_hw[img * 256 + (w + 8 * (k + t))] = r[t] * (1.f / 128.f);
        }
    }
    colp[w][4 * lane + 0] = cs.x;
    colp[w][4 * lane + 1] = cs.y;
    colp[w][4 * lane + 2] = cs.z;
    colp[w][4 * lane + 3] = cs.w;
    __syncthreads();
    if (threadIdx.x < 128) {
        float s = 0.f;
        #pragma unroll
        for (int ww = 0; ww < 8; ww++) s += colp[ww][threadIdx.x];
        d_hw[img * 256 + 128 + threadIdx.x] = s * (1.f / 128.f);
    }
}

// ================= K2 (kA): 1x1 matmul + 3-tap conv + silu =================
// grid 128 (bg), block 256 (l). Conv crosses the h/w concat boundary like the reference.
__global__ __launch_bounds__(256) void kA_mix(const float* __restrict__ w1, const float* __restrict__ b1,
                                              const float* __restrict__ w3, const float* __restrict__ b3) {
    int bg  = blockIdx.x;
    int tid = threadIdx.x;

    __shared__ float hw[16][258];
    __shared__ float w1s[256];
    __shared__ float w3s[768];
    __shared__ float b1s[16], b3s[16];

    #pragma unroll
    for (int c = 0; c < 16; c++) hw[c][tid + 1] = d_hw[(bg * 16 + c) * 256 + tid];
    if (tid < 16) {
        hw[tid][0] = 0.f; hw[tid][257] = 0.f;
        b1s[tid] = b1[tid]; b3s[tid] = b3[tid];
    }
    w1s[tid] = w1[tid];
    for (int idx = tid; idx < 768; idx += 256) w3s[idx] = w3[idx * 3 + 1]; // kw=1
    __syncthreads();

    int l = tid;
    #pragma unroll
    for (int o = 0; o < 16; o++) {
        float a1 = b1s[o], a2 = b3s[o];
        #pragma unroll
        for (int i = 0; i < 16; i++) {
            float h0 = hw[i][l];
            float h1 = hw[i][l + 1];
            float h2 = hw[i][l + 2];
            a1 = fmaf(w1s[o * 16 + i], h1, a1);
            int wb = (o * 16 + i) * 3;
            a2 = fmaf(w3s[wb], h0, fmaf(w3s[wb + 1], h1, fmaf(w3s[wb + 2], h2, a2)));
        }
        d_s1[(bg * 16 + o) * 256 + l] = siluf(a1);
        d_s2[(bg * 16 + o) * 256 + l] = siluf(a2);
    }
}

// ================= K3: per-image separable moment sums =================
// grid 2048 x 256, ascending img order (L2 handoff from K1's tail).
__global__ __launch_bounds__(256) void k3_stats(const float* __restrict__ x) {
    const int img = blockIdx.x;
    const float* g = x + (size_t)img * HWPX;
    const int lane = threadIdx.x & 31, w = threadIdx.x >> 5;
    __shared__ float h1s[128], h2s[128], hq1[128], hq2[128];
    __shared__ float red[8][4];

    if (threadIdx.x < 128) {
        const float a = d_s1[img * 256 + threadIdx.x];
        const float b = d_s2[img * 256 + threadIdx.x];
        h1s[threadIdx.x] = a; hq1[threadIdx.x] = a * a;
        h2s[threadIdx.x] = b; hq2[threadIdx.x] = b * b;
    }
    const float4 wa = __ldg((const float4*)(d_s1 + img * 256 + 128) + lane);
    const float4 wb = __ldg((const float4*)(d_s2 + img * 256 + 128) + lane);
    float4 wa2, wb2;
    wa2.x = wa.x * wa.x; wa2.y = wa.y * wa.y; wa2.z = wa.z * wa.z; wa2.w = wa.w * wa.w;
    wb2.x = wb.x * wb.x; wb2.y = wb.y * wb.y; wb2.z = wb.z * wb.z; wb2.w = wb.w * wb.w;
    __syncthreads();

    float sa = 0.f, qa = 0.f, sb = 0.f, qb = 0.f;
    #pragma unroll
    for (int k = 0; k < 16; k += 4) {
        float4 v[4];
        #pragma unroll
        for (int t = 0; t < 4; t++)
            v[t] = __ldg((const float4*)(g + (w + 8 * (k + t)) * 128) + lane);
        #pragma unroll
        for (int t = 0; t < 4; t++) {
            const int i = w + 8 * (k + t);
            const float h1 = h1s[i], h2 = h2s[i];
            const float h1q = hq1[i], h2q = hq2[i];
            const float v2x = v[t].x * v[t].x, v2y = v[t].y * v[t].y;
            const float v2z = v[t].z * v[t].z, v2w = v[t].w * v[t].w;
            float d1 = v[t].x * wa.x;
            d1 = fmaf(v[t].y, wa.y, d1); d1 = fmaf(v[t].z, wa.z, d1); d1 = fmaf(v[t].w, wa.w, d1);
            float e1 = v2x * wa2.x;
            e1 = fmaf(v2y, wa2.y, e1); e1 = fmaf(v2z, wa2.z, e1); e1 = fmaf(v2w, wa2.w, e1);
            sa = fmaf(h1, d1, sa);
            qa = fmaf(h1q, e1, qa);
            float d2 = v[t].x * wb.x;
            d2 = fmaf(v[t].y, wb.y, d2); d2 = fmaf(v[t].z, wb.z, d2); d2 = fmaf(v[t].w, wb.w, d2);
            float e2 = v2x * wb2.x;
            e2 = fmaf(v2y, wb2.y, e2); e2 = fmaf(v2z, wb2.z, e2); e2 = fmaf(v2w, wb2.w, e2);
            sb = fmaf(h2, d2, sb);
            qb = fmaf(h2q, e2, qb);
        }
    }
    #pragma unroll
    for (int off = 16; off; off >>= 1) {
        sa += __shfl_down_sync(0xffffffffu, sa, off);
        qa += __shfl_down_sync(0xffffffffu, qa, off);
        sb += __shfl_down_sync(0xffffffffu, sb, off);
        qb += __shfl_down_sync(0xffffffffu, qb, off);
    }
    if (lane == 0) { red[w][0] = sa; red[w][1] = qa; red[w][2] = sb; red[w][3] = qb; }
    __syncthreads();
    if (threadIdx.x == 0) {
        float4 st = make_float4(0.f, 0.f, 0.f, 0.f);
        #pragma unroll
        for (int ww = 0; ww < 8; ww++) {
            st.x += red[ww][0]; st.y += red[ww][1];
            st.z += red[ww][2]; st.w += red[ww][3];
        }
        d_stats[img] = st;
    }
}

// ================= K4 (kB): softmax(gn_b) identity + norm scalars =================
__global__ __launch_bounds__(32) void kB_scalars(const float* __restrict__ gn_w, const float* __restrict__ gn_b) {
    int bg = blockIdx.x;
    int c  = threadIdx.x;
    float gb = (c < 16) ? gn_b[c] : -1e30f;
    float m = gb;
    #pragma unroll
    for (int off = 8; off; off >>= 1) m = fmaxf(m, __shfl_xor_sync(0xffffffffu, m, off, 16));
    float e = (c < 16) ? __expf(gb - m) : 0.f;
    float se = e;
    #pragma unroll
    for (int off = 8; off; off >>= 1) se += __shfl_xor_sync(0xffffffffu, se, off, 16);

    float part = 0.f;
    if (c < 16) {
        float a = e / se;                    // a1 == a2 == softmax(gn_b)
        float4 st = d_stats[bg * 16 + c];
        float mu1 = st.x * (1.0f / 16384.0f);
        float v1  = st.y * (1.0f / 16384.0f) - mu1 * mu1;
        float r1  = rsqrtf(v1 + EPSF);
        float mu2 = st.z * (1.0f / 16384.0f);
        float v2  = st.w * (1.0f / 16384.0f) - mu2 * mu2;
        float r2  = rsqrtf(v2 + EPSF);
        float gw  = gn_w[c];
        d_k1[bg * 16 + c] = a * gw * r1;
        d_k2[bg * 16 + c] = a * gw * r2;
        part = a * (2.0f * gn_b[c] - gw * (mu1 * r1 + mu2 * r2));
    }
    #pragma unroll
    for (int off = 16; off; off >>= 1) part += __shfl_down_sync(0xffffffffu, part, off);
    if (c == 0) d_Cc[bg] = part;
}

// ================= K5: wts + gate + output (two-pass slab) =================
// grid (16 slabs, 128 bg) x 256. Reverse bg order (L2 handoff from K3's tail).
// Pass 1: compute wts for the 8-row slab, silu kept in registers.
// Pass 2: re-read slab (L1/L2-hot) and stream stores. regs ~48 -> high occupancy.
__global__ __launch_bounds__(256) void k5_out(const float* __restrict__ x, float* __restrict__ out) {
    const int bg = 127 - blockIdx.y;
    const int i0 = blockIdx.x * 8;
    const int lane = threadIdx.x & 31, w = threadIdx.x >> 5;   // warp w -> row i0+w

    __shared__ float j1[16][128], j2[16][128];
    __shared__ float th1[16][8], th2[16][8];
    __shared__ float Cs;

    for (int idx = threadIdx.x; idx < 2048; idx += 256) {
        const int c = idx >> 7, j = idx & 127;
        j1[c][j] = d_s1[(bg * 16 + c) * 256 + 128 + j];
        j2[c][j] = d_s2[(bg * 16 + c) * 256 + 128 + j];
    }
    if (threadIdx.x < 128) {
        const int c = threadIdx.x >> 3, r = threadIdx.x & 7;
        th1[c][r] = d_k1[bg * 16 + c] * d_s1[(bg * 16 + c) * 256 + i0 + r];
        th2[c][r] = d_k2[bg * 16 + c] * d_s2[(bg * 16 + c) * 256 + i0 + r];
    }
    if (threadIdx.x == 0) Cs = d_Cc[bg];
    __syncthreads();

    const float* xb = x   + (size_t)bg * 16 * HWPX;
    float*       ob = out + (size_t)bg * 16 * HWPX;
    const int row = i0 + w;

    float4 acc = make_float4(Cs, Cs, Cs, Cs);
    #pragma unroll
    for (int c = 0; c < 16; c++) {
        const float4 v = __ldg((const float4*)(xb + c * HWPX + row * 128) + lane);
        const float a1 = th1[c][w], a2 = th2[c][w];
        const float4 ja = *(const float4*)&j1[c][4 * lane];
        const float4 jb = *(const float4*)&j2[c][4 * lane];
        acc.x += v.x * fmaf(a1, ja.x, a2 * jb.x);
        acc.y += v.y * fmaf(a1, ja.y, a2 * jb.y);
        acc.z += v.z * fmaf(a1, ja.z, a2 * jb.z);
        acc.w += v.w * fmaf(a1, ja.w, a2 * jb.w);
    }
    float4 sw;
    sw.x = siluf(acc.x); sw.y = siluf(acc.y); sw.z = siluf(acc.z); sw.w = siluf(acc.w);

    #pragma unroll
    for (int c = 0; c < 16; c++) {
        const float4 v = __ldg((const float4*)(xb + c * HWPX + row * 128) + lane);
        float4 o;
        o.x = v.x * sw.x; o.y = v.y * sw.y;
        o.z = v.z * sw.z; o.w = v.w * sw.w;
        __stcs((float4*)(ob + c * HWPX + row * 128) + lane, o);
    }
}

// ---------------- launch ----------------
extern "C" void kernel_launch(void* const* d_in, const int* in_sizes, int n_in,
                              void* d_out, int out_size) {
    const float* x    = (const float*)d_in[0];
    const float* w1   = (const float*)d_in[1];
    const float* b1   = (const float*)d_in[2];
    const float* w3   = (const float*)d_in[3];
    const float* b3   = (const float*)d_in[4];
    const float* gn_w = (const float*)d_in[5];
    const float* gn_b = (const float*)d_in[6];
    float* out = (float*)d_out;

    k1_means<<<2048, 256>>>(x);
    kA_mix<<<128, 256>>>(w1, b1, w3, b3);
    k3_stats<<<2048, 256>>>(x);
    kB_scalars<<<128, 32>>>(gn_w, gn_b);
    k5_out<<<dim3(16, 128), 256>>>(x, out);
}